// round 15
// baseline (speedup 1.0000x reference)
#include <cuda_runtime.h>
#include <cuda_fp16.h>
#include <cstdint>

#define HH 56
#define WW 56
#define WF 29          // 56/2 + 1
#define BB 32
#define CCH 768
#define NBLK 4
#define SPEC (BB*HH*WF*CCH)
#define SSHRINK 0.01f

typedef unsigned long long ull;

// ---------------- scratch (device globals; no allocation allowed) -------------
__device__ float g_Ar[SPEC];
__device__ float g_Ai[SPEC];
__device__ float g_Br[SPEC];
__device__ float g_Bi[SPEC];

// fp16 MLP-path tensors
__device__ __half g_hXr[SPEC], g_hXi[SPEC];   // fftH-fwd output  (gemm1 input)
__device__ __half g_hHr[SPEC], g_hHi[SPEC];   // layer-1 output   (gemm2 input)
__device__ __half g_hW1[NBLK*384*384], g_hW2[NBLK*384*384];   // [blk][n][k]

// tf32 DFT matrices (padded to mma tiles, pads = 0)
__device__ float g_Ch[64*64],  g_Sh[64*64];    // H-FFT: [k][h], k,h<56
__device__ float g_Cwf[32*64], g_Swfn[32*64];  // fwd rfft W: [kf][w] (Swfn = -sin)
__device__ float g_Cw2[64*32], g_Sw2n[64*32];  // inv rfft W: [w][k] (1/2/1, Sw2n=-a*sin)

__device__ float g_b1[NBLK*384], g_b2[NBLK*384];

__device__ __forceinline__ float to_tf32(float x){
    uint32_t u; asm("cvt.rna.tf32.f32 %0, %1;" : "=r"(u) : "f"(x));
    return __uint_as_float(u);
}
__device__ __forceinline__ uint32_t smem_u32(const void* p) {
    uint32_t a;
    asm("{ .reg .u64 t; cvta.to.shared.u64 t, %1; cvt.u32.u64 %0, t; }" : "=r"(a) : "l"(p));
    return a;
}
#define CP_ASYNC16(sa, gp) \
    asm volatile("cp.async.cg.shared.global [%0], [%1], 16;" :: "r"(sa), "l"(gp))
#define CP_COMMIT() asm volatile("cp.async.commit_group;" ::: "memory")
#define CP_WAIT(n)  asm volatile("cp.async.wait_group %0;" :: "n"(n) : "memory")

__device__ __forceinline__ void mma1688(float c[4], const uint32_t a[4], uint32_t b0, uint32_t b1){
    asm volatile("mma.sync.aligned.m16n8k8.row.col.f32.tf32.tf32.f32 "
        "{%0,%1,%2,%3}, {%4,%5,%6,%7}, {%8,%9}, {%0,%1,%2,%3};"
        : "+f"(c[0]), "+f"(c[1]), "+f"(c[2]), "+f"(c[3])
        : "r"(a[0]), "r"(a[1]), "r"(a[2]), "r"(a[3]), "r"(b0), "r"(b1));
}
__device__ __forceinline__ void mma16816(float c[4], const uint32_t a[4], uint32_t b0, uint32_t b1){
    asm volatile("mma.sync.aligned.m16n8k16.row.col.f32.f16.f16.f32 "
        "{%0,%1,%2,%3}, {%4,%5,%6,%7}, {%8,%9}, {%0,%1,%2,%3};"
        : "+f"(c[0]), "+f"(c[1]), "+f"(c[2]), "+f"(c[3])
        : "r"(a[0]), "r"(a[1]), "r"(a[2]), "r"(a[3]), "r"(b0), "r"(b1));
}

// ---------------- init: tf32 DFT matrices + fp16 transposed weights ----------
__global__ void init_k(const float* __restrict__ w1, const float* __restrict__ b1,
                       const float* __restrict__ w2, const float* __restrict__ b2)
{
    int tid = blockIdx.x*blockDim.x + threadIdx.x;
    int nt  = gridDim.x*blockDim.x;
    const double TW  = 6.283185307179586476925286766559 / 56.0;
    const double INV = 0.13363062095621219234827870598923; // 1/sqrt(56)

    for (int i = tid; i < 64*64; i += nt) {
        int k = i >> 6, h = i & 63;
        float c = 0.f, s = 0.f;
        if (k < 56 && h < 56) {
            int m = (k*h) % 56;
            c = to_tf32((float)(cos(TW*m)*INV));
            s = to_tf32((float)(sin(TW*m)*INV));
        }
        g_Ch[i] = c; g_Sh[i] = s;
    }
    for (int i = tid; i < 32*64; i += nt) {
        int kf = i >> 6, w = i & 63;
        float c = 0.f, s = 0.f;
        if (kf < WF && w < 56) {
            int m = (kf*w) % 56;
            c = to_tf32((float)(cos(TW*m)*INV));
            s = to_tf32((float)(-sin(TW*m)*INV));
        }
        g_Cwf[i] = c; g_Swfn[i] = s;
    }
    for (int i = tid; i < 64*32; i += nt) {
        int w = i >> 5, k = i & 31;
        float c = 0.f, s = 0.f;
        if (w < 56 && k < WF) {
            int m = (k*w) % 56;
            double a = (k==0 || k==WF-1) ? 1.0 : 2.0;
            c = to_tf32((float)(a*cos(TW*m)*INV));
            s = to_tf32((float)(-a*sin(TW*m)*INV));
        }
        g_Cw2[i] = c; g_Sw2n[i] = s;
    }
    for (int i = tid; i < NBLK*384*384; i += nt) {
        int blk = i / (384*384);
        int n   = (i / 384) % 384;
        int kd  = i % 384;
        int r = kd, k = n;
        int d  = (r < 192) ? r : r-192;
        int kk = (k < 192) ? k : k-192;
        float v1, v2;
        if (r < 192) {
            if (k < 192) { v1 =  w1[((0*NBLK+blk)*192+d)*192+kk]; v2 =  w2[((0*NBLK+blk)*192+d)*192+kk]; }
            else         { v1 =  w1[((1*NBLK+blk)*192+d)*192+kk]; v2 =  w2[((1*NBLK+blk)*192+d)*192+kk]; }
        } else {
            if (k < 192) { v1 = -w1[((1*NBLK+blk)*192+d)*192+kk]; v2 = -w2[((1*NBLK+blk)*192+d)*192+kk]; }
            else         { v1 =  w1[((0*NBLK+blk)*192+d)*192+kk]; v2 =  w2[((0*NBLK+blk)*192+d)*192+kk]; }
        }
        g_hW1[i] = __float2half(v1); g_hW2[i] = __float2half(v2);
    }
    for (int i = tid; i < NBLK*384; i += nt) {
        int blk = i / 384, k = i % 384;
        g_b1[i] = (k < 192) ? b1[(0*NBLK+blk)*192 + k] : b1[(1*NBLK+blk)*192 + k-192];
        g_b2[i] = (k < 192) ? b2[(0*NBLK+blk)*192 + k] : b2[(1*NBLK+blk)*192 + k-192];
    }
}

// ========== stage 1: rfft along W — cp.async pipelined, 64-wide chunks =======
#define RW_C   0
#define RW_S   (32*68)
#define RW_X0  (2*32*68)            // 4352
#define RW_BUF (56*72)              // 4032
#define RW_TOT ((2*32*68 + 2*56*72)*4)   // 49664 B -> 4 CTAs/SM

__device__ __forceinline__ void rw_load(uint32_t bS, const float* __restrict__ xb,
                                        int c0, int t)
{
    #pragma unroll
    for (int i = 0; i < 4; i++) {
        int idx = t + i*256;
        if (idx < 896) {                       // 56 rows x 16 quads
            int row = idx >> 4, q = idx & 15;
            CP_ASYNC16(bS + (uint32_t)(row*72 + q*4)*4,
                       &xb[(size_t)row*CCH + c0 + q*4]);
        }
    }
    CP_COMMIT();
}

__global__ void __launch_bounds__(256, 4) rfftWT_k(const float* __restrict__ x)
{
    extern __shared__ float sm[];
    uint32_t smem_base = smem_u32(sm);
    float* Cs = sm + RW_C;
    float* Ss = sm + RW_S;
    int bh = blockIdx.x;
    int t  = threadIdx.x;

    for (int i = t; i < 32*64; i += 256) {
        int r = i >> 6, c = i & 63;
        Cs[r*68+c] = g_Cwf[i]; Ss[r*68+c] = g_Swfn[i];
    }

    const float* xb = x + (size_t)bh*WW*CCH;
    int cbase = blockIdx.y * 4 * 64;

    rw_load(smem_base + (RW_X0 + 0*RW_BUF)*4, xb, cbase,      t);
    rw_load(smem_base + (RW_X0 + 1*RW_BUF)*4, xb, cbase + 64, t);

    int wid = t >> 5, lane = t & 31, g = lane >> 2, tig = lane & 3;
    int warpM = wid & 1, warpN = wid >> 1;   // 2 x 4 (N-tile 16)

    #pragma unroll 1
    for (int c = 0; c < 4; c++) {
        if (c == 3) { CP_WAIT(0); } else { CP_WAIT(1); }
        __syncthreads();
        const float* X = sm + RW_X0 + (c & 1)*RW_BUF;
        int c0 = cbase + c*64;

        float cr[2][4], ci[2][4];
        #pragma unroll
        for (int nt=0;nt<2;nt++)
            #pragma unroll
            for (int j=0;j<4;j++){ cr[nt][j]=0.f; ci[nt][j]=0.f; }

        #pragma unroll
        for (int ks = 0; ks < 7; ks++) {
            int row = warpM*16 + g, col = ks*8 + tig;
            uint32_t aC[4], aS[4];
            aC[0]=__float_as_uint(Cs[row*68+col]);     aC[1]=__float_as_uint(Cs[(row+8)*68+col]);
            aC[2]=__float_as_uint(Cs[row*68+col+4]);   aC[3]=__float_as_uint(Cs[(row+8)*68+col+4]);
            aS[0]=__float_as_uint(Ss[row*68+col]);     aS[1]=__float_as_uint(Ss[(row+8)*68+col]);
            aS[2]=__float_as_uint(Ss[row*68+col+4]);   aS[3]=__float_as_uint(Ss[(row+8)*68+col+4]);
            #pragma unroll
            for (int nt = 0; nt < 2; nt++) {
                int n = warpN*16 + nt*8 + g;
                uint32_t b0 = __float_as_uint(to_tf32(X[(ks*8+tig)*72 + n]));
                uint32_t b1 = __float_as_uint(to_tf32(X[(ks*8+tig+4)*72 + n]));
                mma1688(cr[nt], aC, b0, b1);
                mma1688(ci[nt], aS, b0, b1);
            }
        }

        size_t ob = (size_t)bh*WF*CCH + c0;
        #pragma unroll
        for (int nt = 0; nt < 2; nt++) {
            int n2 = warpN*16 + nt*8 + 2*tig;
            int k0r = warpM*16 + g, k1r = k0r + 8;
            float2 r0 = make_float2(to_tf32(cr[nt][0]), to_tf32(cr[nt][1]));
            float2 i0 = make_float2(to_tf32(ci[nt][0]), to_tf32(ci[nt][1]));
            *(float2*)&g_Ar[ob + (size_t)k0r*CCH + n2] = r0;
            *(float2*)&g_Ai[ob + (size_t)k0r*CCH + n2] = i0;
            if (k1r < WF) {
                float2 r1 = make_float2(to_tf32(cr[nt][2]), to_tf32(cr[nt][3]));
                float2 i1 = make_float2(to_tf32(ci[nt][2]), to_tf32(ci[nt][3]));
                *(float2*)&g_Ar[ob + (size_t)k1r*CCH + n2] = r1;
                *(float2*)&g_Ai[ob + (size_t)k1r*CCH + n2] = i1;
            }
        }

        if (c + 2 < 4) {
            __syncthreads();
            rw_load(smem_base + (RW_X0 + (c & 1)*RW_BUF)*4, xb, c0 + 128, t);
        }
    }
}

// ========== stage 2/5: FFT along H — reg-trig, 3 buffers, 1 barrier/chunk ====
// DIR=0: g_Ar/g_Ai -> fp16 g_hXr/g_hXi.  DIR=1: g_Br/g_Bi -> g_Ar/g_Ai (tf32).
#define FH_XI_OFF (56*72)           // 4032 within buffer
#define FH_BUF (2*56*72)            // 8064 floats
#define FH_TOT (3*FH_BUF*4)         // 96768 B -> 2 CTAs/SM
#define HROW (WF*CCH)   // 22272

__device__ __forceinline__ void fh_load(uint32_t bS,
                                        const float* __restrict__ inR,
                                        const float* __restrict__ inI,
                                        size_t gb, int t)
{
    #pragma unroll
    for (int i = 0; i < 7; i++) {          // 2 arrays x 56 rows x 16 quads = 1792 = 7*256
        int idx = t + i*256;
        int a = (idx >= 896) ? 1 : 0;
        int rem = idx - a*896;
        int row = rem >> 4, q = rem & 15;
        const float* src = a ? inI : inR;
        CP_ASYNC16(bS + (uint32_t)(a*FH_XI_OFF + row*72 + q*4)*4,
                   &src[gb + (size_t)row*HROW + q*4]);
    }
    CP_COMMIT();
}

template<int DIR>
__device__ __forceinline__ void fh_compute(const float* __restrict__ XR,
                                           const float* __restrict__ XI,
                                           const uint32_t aC[7][4], const uint32_t aS[7][4],
                                           size_t base, int warpM, int warpN, int g, int tig)
{
    float cr[4][4], ci[4][4];
    #pragma unroll
    for (int nt=0;nt<4;nt++)
        #pragma unroll
        for (int j=0;j<4;j++){ cr[nt][j]=0.f; ci[nt][j]=0.f; }

    #pragma unroll
    for (int ks = 0; ks < 7; ks++) {
        uint32_t aSn[4];
        #pragma unroll
        for (int j=0;j<4;j++) aSn[j] = aS[ks][j] ^ 0x80000000u;
        #pragma unroll
        for (int nt = 0; nt < 4; nt++) {
            int n = warpN*32 + nt*8 + g;
            uint32_t br0 = __float_as_uint(XR[(ks*8+tig)*72 + n]);
            uint32_t br1 = __float_as_uint(XR[(ks*8+tig+4)*72 + n]);
            uint32_t bi0 = __float_as_uint(XI[(ks*8+tig)*72 + n]);
            uint32_t bi1 = __float_as_uint(XI[(ks*8+tig+4)*72 + n]);
            mma1688(cr[nt], aC[ks],  br0, br1);
            mma1688(cr[nt], aS[ks],  bi0, bi1);
            mma1688(ci[nt], aC[ks],  bi0, bi1);
            mma1688(ci[nt], aSn,     br0, br1);
        }
    }

    int k0r = warpM*16 + g;
    #pragma unroll
    for (int nt = 0; nt < 4; nt++) {
        int n2 = warpN*32 + nt*8 + 2*tig;
        if (DIR == 0) {
            *(__half2*)&g_hXr[base + (size_t)k0r*HROW + n2] = __floats2half2_rn(cr[nt][0], cr[nt][1]);
            *(__half2*)&g_hXi[base + (size_t)k0r*HROW + n2] = __floats2half2_rn(ci[nt][0], ci[nt][1]);
            if (warpM < 3) {
                *(__half2*)&g_hXr[base + (size_t)(k0r+8)*HROW + n2] = __floats2half2_rn(cr[nt][2], cr[nt][3]);
                *(__half2*)&g_hXi[base + (size_t)(k0r+8)*HROW + n2] = __floats2half2_rn(ci[nt][2], ci[nt][3]);
            }
        } else {
            float2 r0 = make_float2(to_tf32(cr[nt][0]), to_tf32(cr[nt][1]));
            float2 i0 = make_float2(to_tf32(ci[nt][0]), to_tf32(ci[nt][1]));
            *(float2*)&g_Ar[base + (size_t)k0r*HROW + n2] = r0;
            *(float2*)&g_Ai[base + (size_t)k0r*HROW + n2] = i0;
            if (warpM < 3) {
                float2 r1 = make_float2(to_tf32(cr[nt][2]), to_tf32(cr[nt][3]));
                float2 i1 = make_float2(to_tf32(ci[nt][2]), to_tf32(ci[nt][3]));
                *(float2*)&g_Ar[base + (size_t)(k0r+8)*HROW + n2] = r1;
                *(float2*)&g_Ai[base + (size_t)(k0r+8)*HROW + n2] = i1;
            }
        }
    }
}

template<int DIR>
__global__ void __launch_bounds__(256, 2) fftHT_k()
{
    extern __shared__ float sm[];
    uint32_t smem_base = smem_u32(sm);
    int b  = blockIdx.x;
    int t  = threadIdx.x;

    const float* inR  = (DIR==0) ? g_Ar : g_Br;
    const float* inI  = (DIR==0) ? g_Ai : g_Bi;

    int wid = t >> 5, lane = t & 31, g = lane >> 2, tig = lane & 3;
    int warpM = wid & 3, warpN = wid >> 2;   // 4 x 2 (N-tile 32)

    uint32_t aC[7][4], aS[7][4];
    {
        int row = warpM*16 + g;
        #pragma unroll
        for (int ks = 0; ks < 7; ks++) {
            int col = ks*8 + tig;
            aC[ks][0]=__float_as_uint(g_Ch[row*64+col]);
            aC[ks][1]=__float_as_uint(g_Ch[(row+8)*64+col]);
            aC[ks][2]=__float_as_uint(g_Ch[row*64+col+4]);
            aC[ks][3]=__float_as_uint(g_Ch[(row+8)*64+col+4]);
            float s0=g_Sh[row*64+col],   s1=g_Sh[(row+8)*64+col];
            float s2=g_Sh[row*64+col+4], s3=g_Sh[(row+8)*64+col+4];
            if (DIR==1){ s0=-s0; s1=-s1; s2=-s2; s3=-s3; }
            aS[ks][0]=__float_as_uint(s0); aS[ks][1]=__float_as_uint(s1);
            aS[ks][2]=__float_as_uint(s2); aS[ks][3]=__float_as_uint(s3);
        }
    }

    size_t bbase = (size_t)b*HH*HROW;
    int jbase = blockIdx.y * 6 * 64;   // T=6

    fh_load(smem_base + (0*FH_BUF)*4, inR, inI, bbase + jbase,      t);
    fh_load(smem_base + (1*FH_BUF)*4, inR, inI, bbase + jbase + 64, t);

    #define FH_STEP(C, BUF, LOADBUF, DO_LOAD, LAST)                              \
        do {                                                                     \
            if (LAST) { CP_WAIT(0); } else { CP_WAIT(1); }                       \
            __syncthreads();                                                     \
            if (DO_LOAD)                                                         \
                fh_load(smem_base + (LOADBUF)*FH_BUF*4, inR, inI,                \
                        bbase + jbase + ((C)+2)*64, t);                          \
            fh_compute<DIR>(sm + (BUF)*FH_BUF, sm + (BUF)*FH_BUF + FH_XI_OFF,    \
                            aC, aS, bbase + jbase + (C)*64,                      \
                            warpM, warpN, g, tig);                               \
        } while (0)

    FH_STEP(0, 0, 2, true,  false);
    FH_STEP(1, 1, 0, true,  false);
    FH_STEP(2, 2, 1, true,  false);
    FH_STEP(3, 0, 2, true,  false);
    FH_STEP(4, 1, 0, false, false);
    FH_STEP(5, 2, 0, false, true);
    #undef FH_STEP
}

// ========== stage 6: inverse rfft along W — cp.async pipelined ===============
#define IW_C   0
#define IW_S   (64*36)
#define IW_B0  (2*64*36)           // 4608
#define IW_XI_OFF (32*72)          // 2304 within buffer
#define IW_BUF (2*32*72)           // 4608
#define IW_TOT ((2*64*36 + 2*2*32*72)*4)   // 55296 B -> 4 CTAs/SM

__device__ __forceinline__ void iw_load(uint32_t bS, size_t gb, int t)
{
    #pragma unroll
    for (int i = 0; i < 4; i++) {          // 2 arrays x 29 rows x 16 quads = 928
        int idx = t + i*256;
        if (idx < 928) {
            int a = (idx >= 464) ? 1 : 0;
            int rem = idx - a*464;
            int row = rem >> 4, q = rem & 15;
            const float* src = a ? g_Ai : g_Ar;
            CP_ASYNC16(bS + (uint32_t)(a*IW_XI_OFF + row*72 + q*4)*4,
                       &src[gb + (size_t)row*CCH + q*4]);
        }
    }
    CP_COMMIT();
}

__global__ void __launch_bounds__(256, 4) irfftWT_k(float* __restrict__ out)
{
    extern __shared__ float sm[];
    uint32_t smem_base = smem_u32(sm);
    float* Cs = sm + IW_C;
    float* Ss = sm + IW_S;
    int bh = blockIdx.x;
    int t  = threadIdx.x;

    for (int i = t; i < 64*32; i += 256) {
        int r = i >> 5, c = i & 31;
        Cs[r*36+c] = g_Cw2[i]; Ss[r*36+c] = g_Sw2n[i];
    }
    for (int i = t; i < 2*2*3*72; i += 256) {
        int bu = i / (2*3*72);
        int rem = i % (2*3*72);
        int a  = rem / (3*72);
        int rr = rem % (3*72);
        sm[IW_B0 + bu*IW_BUF + a*IW_XI_OFF + (29 + rr/72)*72 + (rr%72)] = 0.f;
    }
    __syncthreads();

    size_t ibase = (size_t)bh*WF*CCH;
    int cbase = blockIdx.y * 4 * 64;

    iw_load(smem_base + (IW_B0 + 0*IW_BUF)*4, ibase + cbase,      t);
    iw_load(smem_base + (IW_B0 + 1*IW_BUF)*4, ibase + cbase + 64, t);

    int wid = t >> 5, lane = t & 31, g = lane >> 2, tig = lane & 3;
    int warpM = wid & 3, warpN = wid >> 2;   // 4 x 2 (N-tile 32)

    #pragma unroll 1
    for (int c = 0; c < 4; c++) {
        if (c == 3) { CP_WAIT(0); } else { CP_WAIT(1); }
        __syncthreads();
        const float* XR = sm + IW_B0 + (c & 1)*IW_BUF;
        const float* XI = XR + IW_XI_OFF;
        int c0 = cbase + c*64;

        float co[4][4];
        #pragma unroll
        for (int nt=0;nt<4;nt++)
            #pragma unroll
            for (int j=0;j<4;j++) co[nt][j]=0.f;

        #pragma unroll
        for (int ks = 0; ks < 4; ks++) {
            int row = warpM*16 + g, col = ks*8 + tig;
            uint32_t aC[4], aS[4];
            aC[0]=__float_as_uint(Cs[row*36+col]);     aC[1]=__float_as_uint(Cs[(row+8)*36+col]);
            aC[2]=__float_as_uint(Cs[row*36+col+4]);   aC[3]=__float_as_uint(Cs[(row+8)*36+col+4]);
            aS[0]=__float_as_uint(Ss[row*36+col]);     aS[1]=__float_as_uint(Ss[(row+8)*36+col]);
            aS[2]=__float_as_uint(Ss[row*36+col+4]);   aS[3]=__float_as_uint(Ss[(row+8)*36+col+4]);
            #pragma unroll
            for (int nt = 0; nt < 4; nt++) {
                int n = warpN*32 + nt*8 + g;
                uint32_t br0 = __float_as_uint(XR[(ks*8+tig)*72 + n]);
                uint32_t br1 = __float_as_uint(XR[(ks*8+tig+4)*72 + n]);
                uint32_t bi0 = __float_as_uint(XI[(ks*8+tig)*72 + n]);
                uint32_t bi1 = __float_as_uint(XI[(ks*8+tig+4)*72 + n]);
                mma1688(co[nt], aC, br0, br1);
                mma1688(co[nt], aS, bi0, bi1);
            }
        }

        int w0 = warpM*16 + g;
        size_t ob = (size_t)bh*WW*CCH + c0;
        #pragma unroll
        for (int nt = 0; nt < 4; nt++) {
            int n2 = warpN*32 + nt*8 + 2*tig;
            *(float2*)&out[ob + (size_t)w0*CCH + n2] = make_float2(co[nt][0], co[nt][1]);
            if (warpM < 3)
                *(float2*)&out[ob + (size_t)(w0+8)*CCH + n2] = make_float2(co[nt][2], co[nt][3]);
        }

        if (c + 2 < 4) {
            __syncthreads();
            iw_load(smem_base + (IW_B0 + (c & 1)*IW_BUF)*4, ibase + c0 + 128, t);
        }
    }
}

// ========== MLP GEMM: fp16 m16n8k16, 128x128, 8 warps 64x32, 3-stage ========
#define HGA0 0
#define HGA1 5120
#define HGA2 10240
#define HGB0 15360
#define HGB1 20480
#define HGB2 25600
#define HBIAS_B 61440                 // byte offset of fp32 bias
#define GEMM_SMEM (61440 + 512)       // 61952 B (2 CTAs/SM)

template<int LAYER>
__device__ __forceinline__ void gload(int blk, int p0, int n0, int kc,
                                      uint32_t aS, uint32_t bS, int t)
{
    const __half* inR = (LAYER==1) ? g_hXr : g_hHr;
    const __half* inI = (LAYER==1) ? g_hXi : g_hHi;
    const __half* Wt  = ((LAYER==1) ? g_hW1 : g_hW2) + (size_t)blk*384*384;
    const __half* src = (kc < 6) ? inR : inI;
    int koff = blk*192 + ((kc < 6) ? kc*32 : (kc-6)*32);
    #pragma unroll
    for (int i = 0; i < 2; i++) {      // A: 128 rows x 4 quads (64 B/row) over 256 thr
        int idx = t + i*256;
        int r = idx >> 2, q = idx & 3;
        CP_ASYNC16(aS + (uint32_t)(r*80 + q*16),
                   &src[(size_t)(p0+r)*CCH + koff + q*8]);
    }
    int kb = kc*32;
    #pragma unroll
    for (int i = 0; i < 2; i++) {      // B: 128 rows x 4 quads
        int idx = t + i*256;
        int r = idx >> 2, q = idx & 3;
        CP_ASYNC16(bS + (uint32_t)(r*80 + q*16),
                   &Wt[(size_t)(n0+r)*384 + kb + q*8]);
    }
}

__device__ __forceinline__ void gcompute(const __half* __restrict__ As,
                                         const __half* __restrict__ Bs,
                                         float c[4][4][4],
                                         int warpM, int warpN, int g, int tig)
{
    #pragma unroll
    for (int ks = 0; ks < 2; ks++) {   // 32 halfs per chunk = 2 k16 steps
        uint32_t a[4][4];
        #pragma unroll
        for (int mt = 0; mt < 4; mt++) {
            int r = warpM*64 + mt*16 + g;
            int col = ks*16 + 2*tig;
            a[mt][0] = *(const uint32_t*)&As[r*40 + col];
            a[mt][1] = *(const uint32_t*)&As[(r+8)*40 + col];
            a[mt][2] = *(const uint32_t*)&As[r*40 + col + 8];
            a[mt][3] = *(const uint32_t*)&As[(r+8)*40 + col + 8];
        }
        #pragma unroll
        for (int nt = 0; nt < 4; nt++) {
            int n = warpN*32 + nt*8 + g;
            uint32_t b0 = *(const uint32_t*)&Bs[n*40 + ks*16 + 2*tig];
            uint32_t b1 = *(const uint32_t*)&Bs[n*40 + ks*16 + 2*tig + 8];
            #pragma unroll
            for (int mt = 0; mt < 4; mt++)
                mma16816(c[mt][nt], a[mt], b0, b1);
        }
    }
}

template<int LAYER>
__global__ void __launch_bounds__(256, 2) gemmM_k()
{
    extern __shared__ char smc[];
    __half* smh = (__half*)smc;
    float* sbias = (float*)(smc + HBIAS_B);
    uint32_t smem_base = smem_u32(smc);
    int t = threadIdx.x;
    int wid = t >> 5, lane = t & 31;
    int g = lane >> 2, tig = lane & 3;
    int warpM = wid & 1, warpN = wid >> 1;   // 2 x 4, 64x32 per warp
    int n0  = blockIdx.x * 128;
    int p0  = blockIdx.y * 128;
    int blk = blockIdx.z;

    const float* bias = ((LAYER==1) ? g_b1 : g_b2) + blk*384;
    if (t < 128) sbias[t] = bias[n0 + t];

    float c[4][4][4];
    #pragma unroll
    for (int mt=0;mt<4;mt++)
        #pragma unroll
        for (int nt=0;nt<4;nt++)
            #pragma unroll
            for (int j=0;j<4;j++) c[mt][nt][j] = 0.f;

    gload<LAYER>(blk, p0, n0, 0, smem_base + HGA0*2, smem_base + HGB0*2, t);
    CP_COMMIT();
    gload<LAYER>(blk, p0, n0, 1, smem_base + HGA1*2, smem_base + HGB1*2, t);
    CP_COMMIT();

    #define GEMM_STEP(KC, AOFF, BOFF, NA, NB, DO_LOAD, LAST)                    \
        do {                                                                    \
            if (LAST) { CP_WAIT(0); } else { CP_WAIT(1); }                      \
            __syncthreads();                                                    \
            if (DO_LOAD) {                                                      \
                gload<LAYER>(blk, p0, n0, (KC)+2,                               \
                             smem_base + (NA)*2, smem_base + (NB)*2, t);        \
                CP_COMMIT();                                                    \
            }                                                                   \
            gcompute(smh + (AOFF), smh + (BOFF), c, warpM, warpN, g, tig);      \
        } while (0)

    #pragma unroll 1
    for (int kq = 0; kq < 4; kq++) {
        int kc0 = kq*3;
        GEMM_STEP(kc0+0, HGA0, HGB0, HGA2, HGB2, true,     false);
        GEMM_STEP(kc0+1, HGA1, HGB1, HGA0, HGB0, (kq < 3), false);
        GEMM_STEP(kc0+2, HGA2, HGB2, HGA1, HGB1, (kq < 3), (kq == 3));
    }
    #undef GEMM_STEP

    #pragma unroll
    for (int mt = 0; mt < 4; mt++) {
        #pragma unroll
        for (int rr = 0; rr < 2; rr++) {
            int r = p0 + warpM*64 + mt*16 + rr*8 + g;
            size_t rowoff = (size_t)r*CCH + blk*192;
            #pragma unroll
            for (int nt = 0; nt < 4; nt++) {
                int kl = warpN*32 + nt*8 + 2*tig;
                int ko = n0 + kl;
                float v0 = c[mt][nt][rr*2+0] + sbias[kl];
                float v1 = c[mt][nt][rr*2+1] + sbias[kl + 1];
                int kr = (ko < 192) ? ko : ko - 192;
                if (LAYER == 1) {
                    v0 = fmaxf(v0, 0.f);
                    v1 = fmaxf(v1, 0.f);
                    __half* dst = (ko < 192) ? g_hHr : g_hHi;
                    *(__half2*)&dst[rowoff + kr] = __floats2half2_rn(v0, v1);
                } else {
                    v0 = to_tf32((v0 >  SSHRINK) ? v0-SSHRINK : ((v0 < -SSHRINK) ? v0+SSHRINK : 0.f));
                    v1 = to_tf32((v1 >  SSHRINK) ? v1-SSHRINK : ((v1 < -SSHRINK) ? v1+SSHRINK : 0.f));
                    float* dst = (ko < 192) ? g_Br : g_Bi;
                    *(float2*)&dst[rowoff + kr] = make_float2(v0, v1);
                }
            }
        }
    }
}

// ---------------- launch ------------------------------------------------------
extern "C" void kernel_launch(void* const* d_in, const int* in_sizes, int n_in,
                              void* d_out, int out_size)
{
    const float* x  = (const float*)d_in[0];
    const float* w1 = (const float*)d_in[1];
    const float* b1 = (const float*)d_in[2];
    const float* w2 = (const float*)d_in[3];
    const float* b2 = (const float*)d_in[4];
    float* out = (float*)d_out;

    cudaFuncSetAttribute((const void*)rfftWT_k,   cudaFuncAttributeMaxDynamicSharedMemorySize, RW_TOT);
    cudaFuncSetAttribute((const void*)fftHT_k<0>, cudaFuncAttributeMaxDynamicSharedMemorySize, FH_TOT);
    cudaFuncSetAttribute((const void*)fftHT_k<1>, cudaFuncAttributeMaxDynamicSharedMemorySize, FH_TOT);
    cudaFuncSetAttribute((const void*)irfftWT_k,  cudaFuncAttributeMaxDynamicSharedMemorySize, IW_TOT);
    cudaFuncSetAttribute((const void*)gemmM_k<1>, cudaFuncAttributeMaxDynamicSharedMemorySize, GEMM_SMEM);
    cudaFuncSetAttribute((const void*)gemmM_k<2>, cudaFuncAttributeMaxDynamicSharedMemorySize, GEMM_SMEM);

    init_k<<<512, 256>>>(w1, b1, w2, b2);
    rfftWT_k<<<dim3(BB*HH, 3), 256, RW_TOT>>>(x);
    fftHT_k<0><<<dim3(BB, 58), 256, FH_TOT>>>();
    gemmM_k<1><<<dim3(3, 406, NBLK), 256, GEMM_SMEM>>>();
    gemmM_k<2><<<dim3(3, 406, NBLK), 256, GEMM_SMEM>>>();
    fftHT_k<1><<<dim3(BB, 58), 256, FH_TOT>>>();
    irfftWT_k<<<dim3(BB*HH, 3), 256, IW_TOT>>>(out);
}

// round 16
// speedup vs baseline: 1.0517x; 1.0517x over previous
#include <cuda_runtime.h>
#include <cuda_fp16.h>
#include <cstdint>

#define HH 56
#define WW 56
#define WF 29          // 56/2 + 1
#define BB 32
#define CCH 768
#define NBLK 4
#define SPEC (BB*HH*WF*CCH)
#define SSHRINK 0.01f

typedef unsigned long long ull;

// ---------------- scratch (device globals; no allocation allowed) -------------
__device__ float g_Ar[SPEC];
__device__ float g_Ai[SPEC];
__device__ float g_Br[SPEC];
__device__ float g_Bi[SPEC];

// fp16 MLP-path tensors
__device__ __half g_hXr[SPEC], g_hXi[SPEC];   // fftH-fwd output  (gemm1 input)
__device__ __half g_hHr[SPEC], g_hHi[SPEC];   // layer-1 output   (gemm2 input)
__device__ __half g_hW1[NBLK*384*384], g_hW2[NBLK*384*384];   // [blk][n][k]

// tf32 DFT matrices (padded to mma tiles, pads = 0)
__device__ float g_Ch[64*64],  g_Sh[64*64];    // H-FFT: [k][h], k,h<56
__device__ float g_Cwf[32*64], g_Swfn[32*64];  // fwd rfft W: [kf][w] (Swfn = -sin)
__device__ float g_Cw2[64*32], g_Sw2n[64*32];  // inv rfft W: [w][k] (1/2/1, Sw2n=-a*sin)

__device__ float g_b1[NBLK*384], g_b2[NBLK*384];

__device__ __forceinline__ float to_tf32(float x){
    uint32_t u; asm("cvt.rna.tf32.f32 %0, %1;" : "=r"(u) : "f"(x));
    return __uint_as_float(u);
}
__device__ __forceinline__ uint32_t smem_u32(const void* p) {
    uint32_t a;
    asm("{ .reg .u64 t; cvta.to.shared.u64 t, %1; cvt.u32.u64 %0, t; }" : "=r"(a) : "l"(p));
    return a;
}
#define CP_ASYNC16(sa, gp) \
    asm volatile("cp.async.cg.shared.global [%0], [%1], 16;" :: "r"(sa), "l"(gp))
#define CP_COMMIT() asm volatile("cp.async.commit_group;" ::: "memory")
#define CP_WAIT(n)  asm volatile("cp.async.wait_group %0;" :: "n"(n) : "memory")

__device__ __forceinline__ void mma1688(float c[4], const uint32_t a[4], uint32_t b0, uint32_t b1){
    asm volatile("mma.sync.aligned.m16n8k8.row.col.f32.tf32.tf32.f32 "
        "{%0,%1,%2,%3}, {%4,%5,%6,%7}, {%8,%9}, {%0,%1,%2,%3};"
        : "+f"(c[0]), "+f"(c[1]), "+f"(c[2]), "+f"(c[3])
        : "r"(a[0]), "r"(a[1]), "r"(a[2]), "r"(a[3]), "r"(b0), "r"(b1));
}
__device__ __forceinline__ void mma16816(float c[4], const uint32_t a[4], uint32_t b0, uint32_t b1){
    asm volatile("mma.sync.aligned.m16n8k16.row.col.f32.f16.f16.f32 "
        "{%0,%1,%2,%3}, {%4,%5,%6,%7}, {%8,%9}, {%0,%1,%2,%3};"
        : "+f"(c[0]), "+f"(c[1]), "+f"(c[2]), "+f"(c[3])
        : "r"(a[0]), "r"(a[1]), "r"(a[2]), "r"(a[3]), "r"(b0), "r"(b1));
}

// ---------------- init: tf32 DFT matrices + fp16 transposed weights ----------
__global__ void init_k(const float* __restrict__ w1, const float* __restrict__ b1,
                       const float* __restrict__ w2, const float* __restrict__ b2)
{
    int tid = blockIdx.x*blockDim.x + threadIdx.x;
    int nt  = gridDim.x*blockDim.x;
    const double TW  = 6.283185307179586476925286766559 / 56.0;
    const double INV = 0.13363062095621219234827870598923; // 1/sqrt(56)

    for (int i = tid; i < 64*64; i += nt) {
        int k = i >> 6, h = i & 63;
        float c = 0.f, s = 0.f;
        if (k < 56 && h < 56) {
            int m = (k*h) % 56;
            c = to_tf32((float)(cos(TW*m)*INV));
            s = to_tf32((float)(sin(TW*m)*INV));
        }
        g_Ch[i] = c; g_Sh[i] = s;
    }
    for (int i = tid; i < 32*64; i += nt) {
        int kf = i >> 6, w = i & 63;
        float c = 0.f, s = 0.f;
        if (kf < WF && w < 56) {
            int m = (kf*w) % 56;
            c = to_tf32((float)(cos(TW*m)*INV));
            s = to_tf32((float)(-sin(TW*m)*INV));
        }
        g_Cwf[i] = c; g_Swfn[i] = s;
    }
    for (int i = tid; i < 64*32; i += nt) {
        int w = i >> 5, k = i & 31;
        float c = 0.f, s = 0.f;
        if (w < 56 && k < WF) {
            int m = (k*w) % 56;
            double a = (k==0 || k==WF-1) ? 1.0 : 2.0;
            c = to_tf32((float)(a*cos(TW*m)*INV));
            s = to_tf32((float)(-a*sin(TW*m)*INV));
        }
        g_Cw2[i] = c; g_Sw2n[i] = s;
    }
    for (int i = tid; i < NBLK*384*384; i += nt) {
        int blk = i / (384*384);
        int n   = (i / 384) % 384;
        int kd  = i % 384;
        int r = kd, k = n;
        int d  = (r < 192) ? r : r-192;
        int kk = (k < 192) ? k : k-192;
        float v1, v2;
        if (r < 192) {
            if (k < 192) { v1 =  w1[((0*NBLK+blk)*192+d)*192+kk]; v2 =  w2[((0*NBLK+blk)*192+d)*192+kk]; }
            else         { v1 =  w1[((1*NBLK+blk)*192+d)*192+kk]; v2 =  w2[((1*NBLK+blk)*192+d)*192+kk]; }
        } else {
            if (k < 192) { v1 = -w1[((1*NBLK+blk)*192+d)*192+kk]; v2 = -w2[((1*NBLK+blk)*192+d)*192+kk]; }
            else         { v1 =  w1[((0*NBLK+blk)*192+d)*192+kk]; v2 =  w2[((0*NBLK+blk)*192+d)*192+kk]; }
        }
        g_hW1[i] = __float2half(v1); g_hW2[i] = __float2half(v2);
    }
    for (int i = tid; i < NBLK*384; i += nt) {
        int blk = i / 384, k = i % 384;
        g_b1[i] = (k < 192) ? b1[(0*NBLK+blk)*192 + k] : b1[(1*NBLK+blk)*192 + k-192];
        g_b2[i] = (k < 192) ? b2[(0*NBLK+blk)*192 + k] : b2[(1*NBLK+blk)*192 + k-192];
    }
}

// ========== stage 1: rfft along W — cp.async pipelined, 64-wide chunks =======
#define RW_C   0
#define RW_S   (32*68)
#define RW_X0  (2*32*68)            // 4352
#define RW_BUF (56*72)              // 4032
#define RW_TOT ((2*32*68 + 2*56*72)*4)   // 49664 B -> 4 CTAs/SM

__device__ __forceinline__ void rw_load(uint32_t bS, const float* __restrict__ xb,
                                        int c0, int t)
{
    #pragma unroll
    for (int i = 0; i < 4; i++) {
        int idx = t + i*256;
        if (idx < 896) {                       // 56 rows x 16 quads
            int row = idx >> 4, q = idx & 15;
            CP_ASYNC16(bS + (uint32_t)(row*72 + q*4)*4,
                       &xb[(size_t)row*CCH + c0 + q*4]);
        }
    }
    CP_COMMIT();
}

__global__ void __launch_bounds__(256, 4) rfftWT_k(const float* __restrict__ x)
{
    extern __shared__ float sm[];
    uint32_t smem_base = smem_u32(sm);
    float* Cs = sm + RW_C;
    float* Ss = sm + RW_S;
    int bh = blockIdx.x;
    int t  = threadIdx.x;

    for (int i = t; i < 32*64; i += 256) {
        int r = i >> 6, c = i & 63;
        Cs[r*68+c] = g_Cwf[i]; Ss[r*68+c] = g_Swfn[i];
    }

    const float* xb = x + (size_t)bh*WW*CCH;
    int cbase = blockIdx.y * 4 * 64;

    rw_load(smem_base + (RW_X0 + 0*RW_BUF)*4, xb, cbase,      t);
    rw_load(smem_base + (RW_X0 + 1*RW_BUF)*4, xb, cbase + 64, t);

    int wid = t >> 5, lane = t & 31, g = lane >> 2, tig = lane & 3;
    int warpM = wid & 1, warpN = wid >> 1;   // 2 x 4 (N-tile 16)

    #pragma unroll 1
    for (int c = 0; c < 4; c++) {
        if (c == 3) { CP_WAIT(0); } else { CP_WAIT(1); }
        __syncthreads();
        const float* X = sm + RW_X0 + (c & 1)*RW_BUF;
        int c0 = cbase + c*64;

        float cr[2][4], ci[2][4];
        #pragma unroll
        for (int nt=0;nt<2;nt++)
            #pragma unroll
            for (int j=0;j<4;j++){ cr[nt][j]=0.f; ci[nt][j]=0.f; }

        #pragma unroll
        for (int ks = 0; ks < 7; ks++) {
            int row = warpM*16 + g, col = ks*8 + tig;
            uint32_t aC[4], aS[4];
            aC[0]=__float_as_uint(Cs[row*68+col]);     aC[1]=__float_as_uint(Cs[(row+8)*68+col]);
            aC[2]=__float_as_uint(Cs[row*68+col+4]);   aC[3]=__float_as_uint(Cs[(row+8)*68+col+4]);
            aS[0]=__float_as_uint(Ss[row*68+col]);     aS[1]=__float_as_uint(Ss[(row+8)*68+col]);
            aS[2]=__float_as_uint(Ss[row*68+col+4]);   aS[3]=__float_as_uint(Ss[(row+8)*68+col+4]);
            #pragma unroll
            for (int nt = 0; nt < 2; nt++) {
                int n = warpN*16 + nt*8 + g;
                uint32_t b0 = __float_as_uint(to_tf32(X[(ks*8+tig)*72 + n]));
                uint32_t b1 = __float_as_uint(to_tf32(X[(ks*8+tig+4)*72 + n]));
                mma1688(cr[nt], aC, b0, b1);
                mma1688(ci[nt], aS, b0, b1);
            }
        }

        size_t ob = (size_t)bh*WF*CCH + c0;
        #pragma unroll
        for (int nt = 0; nt < 2; nt++) {
            int n2 = warpN*16 + nt*8 + 2*tig;
            int k0r = warpM*16 + g, k1r = k0r + 8;
            float2 r0 = make_float2(to_tf32(cr[nt][0]), to_tf32(cr[nt][1]));
            float2 i0 = make_float2(to_tf32(ci[nt][0]), to_tf32(ci[nt][1]));
            *(float2*)&g_Ar[ob + (size_t)k0r*CCH + n2] = r0;
            *(float2*)&g_Ai[ob + (size_t)k0r*CCH + n2] = i0;
            if (k1r < WF) {
                float2 r1 = make_float2(to_tf32(cr[nt][2]), to_tf32(cr[nt][3]));
                float2 i1 = make_float2(to_tf32(ci[nt][2]), to_tf32(ci[nt][3]));
                *(float2*)&g_Ar[ob + (size_t)k1r*CCH + n2] = r1;
                *(float2*)&g_Ai[ob + (size_t)k1r*CCH + n2] = i1;
            }
        }

        if (c + 2 < 4) {
            __syncthreads();
            rw_load(smem_base + (RW_X0 + (c & 1)*RW_BUF)*4, xb, c0 + 128, t);
        }
    }
}

// ========== stage 2/5: FFT along H — reg-trig, 3 buffers, 1 barrier/chunk ====
// DIR=0: g_Ar/g_Ai -> fp16 g_hXr/g_hXi.  DIR=1: g_Br/g_Bi -> g_Ar/g_Ai (tf32).
#define FH_XI_OFF (56*72)           // 4032 within buffer
#define FH_BUF (2*56*72)            // 8064 floats
#define FH_TOT (3*FH_BUF*4)         // 96768 B -> 2 CTAs/SM
#define HROW (WF*CCH)   // 22272

__device__ __forceinline__ void fh_load(uint32_t bS,
                                        const float* __restrict__ inR,
                                        const float* __restrict__ inI,
                                        size_t gb, int t)
{
    #pragma unroll
    for (int i = 0; i < 7; i++) {          // 2 arrays x 56 rows x 16 quads = 1792 = 7*256
        int idx = t + i*256;
        int a = (idx >= 896) ? 1 : 0;
        int rem = idx - a*896;
        int row = rem >> 4, q = rem & 15;
        const float* src = a ? inI : inR;
        CP_ASYNC16(bS + (uint32_t)(a*FH_XI_OFF + row*72 + q*4)*4,
                   &src[gb + (size_t)row*HROW + q*4]);
    }
    CP_COMMIT();
}

template<int DIR>
__device__ __forceinline__ void fh_compute(const float* __restrict__ XR,
                                           const float* __restrict__ XI,
                                           const uint32_t aC[7][4], const uint32_t aS[7][4],
                                           size_t base, int warpM, int warpN, int g, int tig)
{
    float cr[4][4], ci[4][4];
    #pragma unroll
    for (int nt=0;nt<4;nt++)
        #pragma unroll
        for (int j=0;j<4;j++){ cr[nt][j]=0.f; ci[nt][j]=0.f; }

    #pragma unroll
    for (int ks = 0; ks < 7; ks++) {
        uint32_t aSn[4];
        #pragma unroll
        for (int j=0;j<4;j++) aSn[j] = aS[ks][j] ^ 0x80000000u;
        #pragma unroll
        for (int nt = 0; nt < 4; nt++) {
            int n = warpN*32 + nt*8 + g;
            uint32_t br0 = __float_as_uint(XR[(ks*8+tig)*72 + n]);
            uint32_t br1 = __float_as_uint(XR[(ks*8+tig+4)*72 + n]);
            uint32_t bi0 = __float_as_uint(XI[(ks*8+tig)*72 + n]);
            uint32_t bi1 = __float_as_uint(XI[(ks*8+tig+4)*72 + n]);
            mma1688(cr[nt], aC[ks],  br0, br1);
            mma1688(cr[nt], aS[ks],  bi0, bi1);
            mma1688(ci[nt], aC[ks],  bi0, bi1);
            mma1688(ci[nt], aSn,     br0, br1);
        }
    }

    int k0r = warpM*16 + g;
    #pragma unroll
    for (int nt = 0; nt < 4; nt++) {
        int n2 = warpN*32 + nt*8 + 2*tig;
        if (DIR == 0) {
            *(__half2*)&g_hXr[base + (size_t)k0r*HROW + n2] = __floats2half2_rn(cr[nt][0], cr[nt][1]);
            *(__half2*)&g_hXi[base + (size_t)k0r*HROW + n2] = __floats2half2_rn(ci[nt][0], ci[nt][1]);
            if (warpM < 3) {
                *(__half2*)&g_hXr[base + (size_t)(k0r+8)*HROW + n2] = __floats2half2_rn(cr[nt][2], cr[nt][3]);
                *(__half2*)&g_hXi[base + (size_t)(k0r+8)*HROW + n2] = __floats2half2_rn(ci[nt][2], ci[nt][3]);
            }
        } else {
            float2 r0 = make_float2(to_tf32(cr[nt][0]), to_tf32(cr[nt][1]));
            float2 i0 = make_float2(to_tf32(ci[nt][0]), to_tf32(ci[nt][1]));
            *(float2*)&g_Ar[base + (size_t)k0r*HROW + n2] = r0;
            *(float2*)&g_Ai[base + (size_t)k0r*HROW + n2] = i0;
            if (warpM < 3) {
                float2 r1 = make_float2(to_tf32(cr[nt][2]), to_tf32(cr[nt][3]));
                float2 i1 = make_float2(to_tf32(ci[nt][2]), to_tf32(ci[nt][3]));
                *(float2*)&g_Ar[base + (size_t)(k0r+8)*HROW + n2] = r1;
                *(float2*)&g_Ai[base + (size_t)(k0r+8)*HROW + n2] = i1;
            }
        }
    }
}

template<int DIR>
__global__ void __launch_bounds__(256, 2) fftHT_k()
{
    extern __shared__ float sm[];
    uint32_t smem_base = smem_u32(sm);
    int b  = blockIdx.x;
    int t  = threadIdx.x;

    const float* inR  = (DIR==0) ? g_Ar : g_Br;
    const float* inI  = (DIR==0) ? g_Ai : g_Bi;

    int wid = t >> 5, lane = t & 31, g = lane >> 2, tig = lane & 3;
    int warpM = wid & 3, warpN = wid >> 2;   // 4 x 2 (N-tile 32)

    uint32_t aC[7][4], aS[7][4];
    {
        int row = warpM*16 + g;
        #pragma unroll
        for (int ks = 0; ks < 7; ks++) {
            int col = ks*8 + tig;
            aC[ks][0]=__float_as_uint(g_Ch[row*64+col]);
            aC[ks][1]=__float_as_uint(g_Ch[(row+8)*64+col]);
            aC[ks][2]=__float_as_uint(g_Ch[row*64+col+4]);
            aC[ks][3]=__float_as_uint(g_Ch[(row+8)*64+col+4]);
            float s0=g_Sh[row*64+col],   s1=g_Sh[(row+8)*64+col];
            float s2=g_Sh[row*64+col+4], s3=g_Sh[(row+8)*64+col+4];
            if (DIR==1){ s0=-s0; s1=-s1; s2=-s2; s3=-s3; }
            aS[ks][0]=__float_as_uint(s0); aS[ks][1]=__float_as_uint(s1);
            aS[ks][2]=__float_as_uint(s2); aS[ks][3]=__float_as_uint(s3);
        }
    }

    size_t bbase = (size_t)b*HH*HROW;
    int jbase = blockIdx.y * 6 * 64;   // T=6

    fh_load(smem_base + (0*FH_BUF)*4, inR, inI, bbase + jbase,      t);
    fh_load(smem_base + (1*FH_BUF)*4, inR, inI, bbase + jbase + 64, t);

    #define FH_STEP(C, BUF, LOADBUF, DO_LOAD, LAST)                              \
        do {                                                                     \
            if (LAST) { CP_WAIT(0); } else { CP_WAIT(1); }                       \
            __syncthreads();                                                     \
            if (DO_LOAD)                                                         \
                fh_load(smem_base + (LOADBUF)*FH_BUF*4, inR, inI,                \
                        bbase + jbase + ((C)+2)*64, t);                          \
            fh_compute<DIR>(sm + (BUF)*FH_BUF, sm + (BUF)*FH_BUF + FH_XI_OFF,    \
                            aC, aS, bbase + jbase + (C)*64,                      \
                            warpM, warpN, g, tig);                               \
        } while (0)

    FH_STEP(0, 0, 2, true,  false);
    FH_STEP(1, 1, 0, true,  false);
    FH_STEP(2, 2, 1, true,  false);
    FH_STEP(3, 0, 2, true,  false);
    FH_STEP(4, 1, 0, false, false);
    FH_STEP(5, 2, 0, false, true);
    #undef FH_STEP
}

// ========== stage 6: inverse rfft along W — cp.async pipelined ===============
#define IW_C   0
#define IW_S   (64*36)
#define IW_B0  (2*64*36)           // 4608
#define IW_XI_OFF (32*72)          // 2304 within buffer
#define IW_BUF (2*32*72)           // 4608
#define IW_TOT ((2*64*36 + 2*2*32*72)*4)   // 55296 B -> 4 CTAs/SM

__device__ __forceinline__ void iw_load(uint32_t bS, size_t gb, int t)
{
    #pragma unroll
    for (int i = 0; i < 4; i++) {          // 2 arrays x 29 rows x 16 quads = 928
        int idx = t + i*256;
        if (idx < 928) {
            int a = (idx >= 464) ? 1 : 0;
            int rem = idx - a*464;
            int row = rem >> 4, q = rem & 15;
            const float* src = a ? g_Ai : g_Ar;
            CP_ASYNC16(bS + (uint32_t)(a*IW_XI_OFF + row*72 + q*4)*4,
                       &src[gb + (size_t)row*CCH + q*4]);
        }
    }
    CP_COMMIT();
}

__global__ void __launch_bounds__(256, 4) irfftWT_k(float* __restrict__ out)
{
    extern __shared__ float sm[];
    uint32_t smem_base = smem_u32(sm);
    float* Cs = sm + IW_C;
    float* Ss = sm + IW_S;
    int bh = blockIdx.x;
    int t  = threadIdx.x;

    for (int i = t; i < 64*32; i += 256) {
        int r = i >> 5, c = i & 31;
        Cs[r*36+c] = g_Cw2[i]; Ss[r*36+c] = g_Sw2n[i];
    }
    for (int i = t; i < 2*2*3*72; i += 256) {
        int bu = i / (2*3*72);
        int rem = i % (2*3*72);
        int a  = rem / (3*72);
        int rr = rem % (3*72);
        sm[IW_B0 + bu*IW_BUF + a*IW_XI_OFF + (29 + rr/72)*72 + (rr%72)] = 0.f;
    }
    __syncthreads();

    size_t ibase = (size_t)bh*WF*CCH;
    int cbase = blockIdx.y * 4 * 64;

    iw_load(smem_base + (IW_B0 + 0*IW_BUF)*4, ibase + cbase,      t);
    iw_load(smem_base + (IW_B0 + 1*IW_BUF)*4, ibase + cbase + 64, t);

    int wid = t >> 5, lane = t & 31, g = lane >> 2, tig = lane & 3;
    int warpM = wid & 3, warpN = wid >> 2;   // 4 x 2 (N-tile 32)

    #pragma unroll 1
    for (int c = 0; c < 4; c++) {
        if (c == 3) { CP_WAIT(0); } else { CP_WAIT(1); }
        __syncthreads();
        const float* XR = sm + IW_B0 + (c & 1)*IW_BUF;
        const float* XI = XR + IW_XI_OFF;
        int c0 = cbase + c*64;

        float co[4][4];
        #pragma unroll
        for (int nt=0;nt<4;nt++)
            #pragma unroll
            for (int j=0;j<4;j++) co[nt][j]=0.f;

        #pragma unroll
        for (int ks = 0; ks < 4; ks++) {
            int row = warpM*16 + g, col = ks*8 + tig;
            uint32_t aC[4], aS[4];
            aC[0]=__float_as_uint(Cs[row*36+col]);     aC[1]=__float_as_uint(Cs[(row+8)*36+col]);
            aC[2]=__float_as_uint(Cs[row*36+col+4]);   aC[3]=__float_as_uint(Cs[(row+8)*36+col+4]);
            aS[0]=__float_as_uint(Ss[row*36+col]);     aS[1]=__float_as_uint(Ss[(row+8)*36+col]);
            aS[2]=__float_as_uint(Ss[row*36+col+4]);   aS[3]=__float_as_uint(Ss[(row+8)*36+col+4]);
            #pragma unroll
            for (int nt = 0; nt < 4; nt++) {
                int n = warpN*32 + nt*8 + g;
                uint32_t br0 = __float_as_uint(XR[(ks*8+tig)*72 + n]);
                uint32_t br1 = __float_as_uint(XR[(ks*8+tig+4)*72 + n]);
                uint32_t bi0 = __float_as_uint(XI[(ks*8+tig)*72 + n]);
                uint32_t bi1 = __float_as_uint(XI[(ks*8+tig+4)*72 + n]);
                mma1688(co[nt], aC, br0, br1);
                mma1688(co[nt], aS, bi0, bi1);
            }
        }

        int w0 = warpM*16 + g;
        size_t ob = (size_t)bh*WW*CCH + c0;
        #pragma unroll
        for (int nt = 0; nt < 4; nt++) {
            int n2 = warpN*32 + nt*8 + 2*tig;
            *(float2*)&out[ob + (size_t)w0*CCH + n2] = make_float2(co[nt][0], co[nt][1]);
            if (warpM < 3)
                *(float2*)&out[ob + (size_t)(w0+8)*CCH + n2] = make_float2(co[nt][2], co[nt][3]);
        }

        if (c + 2 < 4) {
            __syncthreads();
            iw_load(smem_base + (IW_B0 + (c & 1)*IW_BUF)*4, ibase + c0 + 128, t);
        }
    }
}

// ========== MLP GEMM: fp16 m16n8k16, 128x128, 8 warps 64x32, 4-stage ========
#define HSTG 10240                    // halfs per stage (A 5120 + B 5120)
#define HBIAS_B 81920                 // byte offset of fp32 bias (4 stages * 20480 B)
#define GEMM_SMEM (81920 + 512)       // 82432 B (2 CTAs/SM)

template<int LAYER>
__device__ __forceinline__ void gload(int blk, int p0, int n0, int kc,
                                      uint32_t aS, uint32_t bS, int t)
{
    const __half* inR = (LAYER==1) ? g_hXr : g_hHr;
    const __half* inI = (LAYER==1) ? g_hXi : g_hHi;
    const __half* Wt  = ((LAYER==1) ? g_hW1 : g_hW2) + (size_t)blk*384*384;
    const __half* src = (kc < 6) ? inR : inI;
    int koff = blk*192 + ((kc < 6) ? kc*32 : (kc-6)*32);
    #pragma unroll
    for (int i = 0; i < 2; i++) {      // A: 128 rows x 4 quads (64 B/row)
        int idx = t + i*256;
        int r = idx >> 2, q = idx & 3;
        CP_ASYNC16(aS + (uint32_t)(r*80 + q*16),
                   &src[(size_t)(p0+r)*CCH + koff + q*8]);
    }
    int kb = kc*32;
    #pragma unroll
    for (int i = 0; i < 2; i++) {      // B: 128 rows x 4 quads
        int idx = t + i*256;
        int r = idx >> 2, q = idx & 3;
        CP_ASYNC16(bS + (uint32_t)(r*80 + q*16),
                   &Wt[(size_t)(n0+r)*384 + kb + q*8]);
    }
}

__device__ __forceinline__ void gcompute(const __half* __restrict__ As,
                                         const __half* __restrict__ Bs,
                                         float c[4][4][4],
                                         int warpM, int warpN, int g, int tig)
{
    #pragma unroll
    for (int ks = 0; ks < 2; ks++) {   // 32 halfs per chunk = 2 k16 steps
        uint32_t a[4][4];
        #pragma unroll
        for (int mt = 0; mt < 4; mt++) {
            int r = warpM*64 + mt*16 + g;
            int col = ks*16 + 2*tig;
            a[mt][0] = *(const uint32_t*)&As[r*40 + col];
            a[mt][1] = *(const uint32_t*)&As[(r+8)*40 + col];
            a[mt][2] = *(const uint32_t*)&As[r*40 + col + 8];
            a[mt][3] = *(const uint32_t*)&As[(r+8)*40 + col + 8];
        }
        #pragma unroll
        for (int nt = 0; nt < 4; nt++) {
            int n = warpN*32 + nt*8 + g;
            uint32_t b0 = *(const uint32_t*)&Bs[n*40 + ks*16 + 2*tig];
            uint32_t b1 = *(const uint32_t*)&Bs[n*40 + ks*16 + 2*tig + 8];
            #pragma unroll
            for (int mt = 0; mt < 4; mt++)
                mma16816(c[mt][nt], a[mt], b0, b1);
        }
    }
}

template<int LAYER>
__global__ void __launch_bounds__(256, 2) gemmM_k()
{
    extern __shared__ char smc[];
    __half* smh = (__half*)smc;
    float* sbias = (float*)(smc + HBIAS_B);
    uint32_t smem_base = smem_u32(smc);
    int t = threadIdx.x;
    int wid = t >> 5, lane = t & 31;
    int g = lane >> 2, tig = lane & 3;
    int warpM = wid & 1, warpN = wid >> 1;   // 2 x 4, 64x32 per warp
    int n0  = blockIdx.x * 128;
    int p0  = blockIdx.y * 128;
    int blk = blockIdx.z;

    const float* bias = ((LAYER==1) ? g_b1 : g_b2) + blk*384;
    if (t < 128) sbias[t] = bias[n0 + t];

    float c[4][4][4];
    #pragma unroll
    for (int mt=0;mt<4;mt++)
        #pragma unroll
        for (int nt=0;nt<4;nt++)
            #pragma unroll
            for (int j=0;j<4;j++) c[mt][nt][j] = 0.f;

    // prologue: 3 chunks in flight
    gload<LAYER>(blk, p0, n0, 0, smem_base + (0*HSTG)*2, smem_base + (0*HSTG + 5120)*2, t);
    CP_COMMIT();
    gload<LAYER>(blk, p0, n0, 1, smem_base + (1*HSTG)*2, smem_base + (1*HSTG + 5120)*2, t);
    CP_COMMIT();
    gload<LAYER>(blk, p0, n0, 2, smem_base + (2*HSTG)*2, smem_base + (2*HSTG + 5120)*2, t);
    CP_COMMIT();

    // chunk kc uses buffer kc%4; load kc+3 into (kc+3)%4 after barrier.
    #define GEMM_STEP(KC, BUF, LBUF, DO_LOAD, WAITN)                            \
        do {                                                                    \
            CP_WAIT(WAITN);                                                     \
            __syncthreads();                                                    \
            if (DO_LOAD) {                                                      \
                gload<LAYER>(blk, p0, n0, (KC)+3,                               \
                             smem_base + ((LBUF)*HSTG)*2,                       \
                             smem_base + ((LBUF)*HSTG + 5120)*2, t);            \
                CP_COMMIT();                                                    \
            }                                                                   \
            gcompute(smh + (BUF)*HSTG, smh + (BUF)*HSTG + 5120,                 \
                     c, warpM, warpN, g, tig);                                  \
        } while (0)

    GEMM_STEP(0,  0, 3, true,  2);
    GEMM_STEP(1,  1, 0, true,  2);
    GEMM_STEP(2,  2, 1, true,  2);
    GEMM_STEP(3,  3, 2, true,  2);
    GEMM_STEP(4,  0, 3, true,  2);
    GEMM_STEP(5,  1, 0, true,  2);
    GEMM_STEP(6,  2, 1, true,  2);
    GEMM_STEP(7,  3, 2, true,  2);
    GEMM_STEP(8,  0, 3, true,  2);
    GEMM_STEP(9,  1, 0, false, 2);
    GEMM_STEP(10, 2, 0, false, 1);
    GEMM_STEP(11, 3, 0, false, 0);
    #undef GEMM_STEP

    #pragma unroll
    for (int mt = 0; mt < 4; mt++) {
        #pragma unroll
        for (int rr = 0; rr < 2; rr++) {
            int r = p0 + warpM*64 + mt*16 + rr*8 + g;
            size_t rowoff = (size_t)r*CCH + blk*192;
            #pragma unroll
            for (int nt = 0; nt < 4; nt++) {
                int kl = warpN*32 + nt*8 + 2*tig;
                int ko = n0 + kl;
                float v0 = c[mt][nt][rr*2+0] + sbias[kl];
                float v1 = c[mt][nt][rr*2+1] + sbias[kl + 1];
                int kr = (ko < 192) ? ko : ko - 192;
                if (LAYER == 1) {
                    v0 = fmaxf(v0, 0.f);
                    v1 = fmaxf(v1, 0.f);
                    __half* dst = (ko < 192) ? g_hHr : g_hHi;
                    *(__half2*)&dst[rowoff + kr] = __floats2half2_rn(v0, v1);
                } else {
                    v0 = to_tf32((v0 >  SSHRINK) ? v0-SSHRINK : ((v0 < -SSHRINK) ? v0+SSHRINK : 0.f));
                    v1 = to_tf32((v1 >  SSHRINK) ? v1-SSHRINK : ((v1 < -SSHRINK) ? v1+SSHRINK : 0.f));
                    float* dst = (ko < 192) ? g_Br : g_Bi;
                    *(float2*)&dst[rowoff + kr] = make_float2(v0, v1);
                }
            }
        }
    }
}

// ---------------- launch ------------------------------------------------------
extern "C" void kernel_launch(void* const* d_in, const int* in_sizes, int n_in,
                              void* d_out, int out_size)
{
    const float* x  = (const float*)d_in[0];
    const float* w1 = (const float*)d_in[1];
    const float* b1 = (const float*)d_in[2];
    const float* w2 = (const float*)d_in[3];
    const float* b2 = (const float*)d_in[4];
    float* out = (float*)d_out;

    cudaFuncSetAttribute((const void*)rfftWT_k,   cudaFuncAttributeMaxDynamicSharedMemorySize, RW_TOT);
    cudaFuncSetAttribute((const void*)fftHT_k<0>, cudaFuncAttributeMaxDynamicSharedMemorySize, FH_TOT);
    cudaFuncSetAttribute((const void*)fftHT_k<1>, cudaFuncAttributeMaxDynamicSharedMemorySize, FH_TOT);
    cudaFuncSetAttribute((const void*)irfftWT_k,  cudaFuncAttributeMaxDynamicSharedMemorySize, IW_TOT);
    cudaFuncSetAttribute((const void*)gemmM_k<1>, cudaFuncAttributeMaxDynamicSharedMemorySize, GEMM_SMEM);
    cudaFuncSetAttribute((const void*)gemmM_k<2>, cudaFuncAttributeMaxDynamicSharedMemorySize, GEMM_SMEM);

    init_k<<<512, 256>>>(w1, b1, w2, b2);
    rfftWT_k<<<dim3(BB*HH, 3), 256, RW_TOT>>>(x);
    fftHT_k<0><<<dim3(BB, 58), 256, FH_TOT>>>();
    gemmM_k<1><<<dim3(3, 406, NBLK), 256, GEMM_SMEM>>>();
    gemmM_k<2><<<dim3(3, 406, NBLK), 256, GEMM_SMEM>>>();
    fftHT_k<1><<<dim3(BB, 58), 256, FH_TOT>>>();
    irfftWT_k<<<dim3(BB*HH, 3), 256, IW_TOT>>>(out);
}

// round 17
// speedup vs baseline: 1.0818x; 1.0286x over previous
#include <cuda_runtime.h>
#include <cuda_fp16.h>
#include <cstdint>

#define HH 56
#define WW 56
#define WF 29          // 56/2 + 1
#define BB 32
#define CCH 768
#define NBLK 4
#define SPEC (BB*HH*WF*CCH)
#define SSHRINK 0.01f

typedef unsigned long long ull;

// ---------------- scratch (device globals; no allocation allowed) -------------
__device__ float g_Ar[SPEC];
__device__ float g_Ai[SPEC];
__device__ float g_Br[SPEC];
__device__ float g_Bi[SPEC];

// fp16 MLP-path tensors
__device__ __half g_hXr[SPEC], g_hXi[SPEC];   // fftH-fwd output  (gemm1 input)
__device__ __half g_hHr[SPEC], g_hHi[SPEC];   // layer-1 output   (gemm2 input)
__device__ __half g_hW1[NBLK*384*384], g_hW2[NBLK*384*384];   // [blk][n][k]

// tf32 DFT matrices (padded to mma tiles, pads = 0)
__device__ float g_Ch[64*64],  g_Sh[64*64];    // H-FFT: [k][h], k,h<56
__device__ float g_Cwf[32*64], g_Swfn[32*64];  // fwd rfft W: [kf][w] (Swfn = -sin)
__device__ float g_Cw2[64*32], g_Sw2n[64*32];  // inv rfft W: [w][k] (1/2/1, Sw2n=-a*sin)

__device__ float g_b1[NBLK*384], g_b2[NBLK*384];

__device__ __forceinline__ float to_tf32(float x){
    uint32_t u; asm("cvt.rna.tf32.f32 %0, %1;" : "=r"(u) : "f"(x));
    return __uint_as_float(u);
}
__device__ __forceinline__ uint32_t smem_u32(const void* p) {
    uint32_t a;
    asm("{ .reg .u64 t; cvta.to.shared.u64 t, %1; cvt.u32.u64 %0, t; }" : "=r"(a) : "l"(p));
    return a;
}
#define CP_ASYNC16(sa, gp) \
    asm volatile("cp.async.cg.shared.global [%0], [%1], 16;" :: "r"(sa), "l"(gp))
#define CP_COMMIT() asm volatile("cp.async.commit_group;" ::: "memory")
#define CP_WAIT(n)  asm volatile("cp.async.wait_group %0;" :: "n"(n) : "memory")

__device__ __forceinline__ void mma1688(float c[4], const uint32_t a[4], uint32_t b0, uint32_t b1){
    asm volatile("mma.sync.aligned.m16n8k8.row.col.f32.tf32.tf32.f32 "
        "{%0,%1,%2,%3}, {%4,%5,%6,%7}, {%8,%9}, {%0,%1,%2,%3};"
        : "+f"(c[0]), "+f"(c[1]), "+f"(c[2]), "+f"(c[3])
        : "r"(a[0]), "r"(a[1]), "r"(a[2]), "r"(a[3]), "r"(b0), "r"(b1));
}
__device__ __forceinline__ void mma16816(float c[4], const uint32_t a[4], uint32_t b0, uint32_t b1){
    asm volatile("mma.sync.aligned.m16n8k16.row.col.f32.f16.f16.f32 "
        "{%0,%1,%2,%3}, {%4,%5,%6,%7}, {%8,%9}, {%0,%1,%2,%3};"
        : "+f"(c[0]), "+f"(c[1]), "+f"(c[2]), "+f"(c[3])
        : "r"(a[0]), "r"(a[1]), "r"(a[2]), "r"(a[3]), "r"(b0), "r"(b1));
}

// ---------------- init: tf32 DFT matrices + fp16 transposed weights ----------
__global__ void init_k(const float* __restrict__ w1, const float* __restrict__ b1,
                       const float* __restrict__ w2, const float* __restrict__ b2)
{
    int tid = blockIdx.x*blockDim.x + threadIdx.x;
    int nt  = gridDim.x*blockDim.x;
    const double TW  = 6.283185307179586476925286766559 / 56.0;
    const double INV = 0.13363062095621219234827870598923; // 1/sqrt(56)

    for (int i = tid; i < 64*64; i += nt) {
        int k = i >> 6, h = i & 63;
        float c = 0.f, s = 0.f;
        if (k < 56 && h < 56) {
            int m = (k*h) % 56;
            c = to_tf32((float)(cos(TW*m)*INV));
            s = to_tf32((float)(sin(TW*m)*INV));
        }
        g_Ch[i] = c; g_Sh[i] = s;
    }
    for (int i = tid; i < 32*64; i += nt) {
        int kf = i >> 6, w = i & 63;
        float c = 0.f, s = 0.f;
        if (kf < WF && w < 56) {
            int m = (kf*w) % 56;
            c = to_tf32((float)(cos(TW*m)*INV));
            s = to_tf32((float)(-sin(TW*m)*INV));
        }
        g_Cwf[i] = c; g_Swfn[i] = s;
    }
    for (int i = tid; i < 64*32; i += nt) {
        int w = i >> 5, k = i & 31;
        float c = 0.f, s = 0.f;
        if (w < 56 && k < WF) {
            int m = (k*w) % 56;
            double a = (k==0 || k==WF-1) ? 1.0 : 2.0;
            c = to_tf32((float)(a*cos(TW*m)*INV));
            s = to_tf32((float)(-a*sin(TW*m)*INV));
        }
        g_Cw2[i] = c; g_Sw2n[i] = s;
    }
    for (int i = tid; i < NBLK*384*384; i += nt) {
        int blk = i / (384*384);
        int n   = (i / 384) % 384;
        int kd  = i % 384;
        int r = kd, k = n;
        int d  = (r < 192) ? r : r-192;
        int kk = (k < 192) ? k : k-192;
        float v1, v2;
        if (r < 192) {
            if (k < 192) { v1 =  w1[((0*NBLK+blk)*192+d)*192+kk]; v2 =  w2[((0*NBLK+blk)*192+d)*192+kk]; }
            else         { v1 =  w1[((1*NBLK+blk)*192+d)*192+kk]; v2 =  w2[((1*NBLK+blk)*192+d)*192+kk]; }
        } else {
            if (k < 192) { v1 = -w1[((1*NBLK+blk)*192+d)*192+kk]; v2 = -w2[((1*NBLK+blk)*192+d)*192+kk]; }
            else         { v1 =  w1[((0*NBLK+blk)*192+d)*192+kk]; v2 =  w2[((0*NBLK+blk)*192+d)*192+kk]; }
        }
        g_hW1[i] = __float2half(v1); g_hW2[i] = __float2half(v2);
    }
    for (int i = tid; i < NBLK*384; i += nt) {
        int blk = i / 384, k = i % 384;
        g_b1[i] = (k < 192) ? b1[(0*NBLK+blk)*192 + k] : b1[(1*NBLK+blk)*192 + k-192];
        g_b2[i] = (k < 192) ? b2[(0*NBLK+blk)*192 + k] : b2[(1*NBLK+blk)*192 + k-192];
    }
}

// ========== stage 1: rfft along W — cp.async pipelined, 64-wide chunks =======
#define RW_C   0
#define RW_S   (32*68)
#define RW_X0  (2*32*68)            // 4352
#define RW_BUF (56*72)              // 4032
#define RW_TOT ((2*32*68 + 2*56*72)*4)   // 49664 B -> 4 CTAs/SM

__device__ __forceinline__ void rw_load(uint32_t bS, const float* __restrict__ xb,
                                        int c0, int t)
{
    #pragma unroll
    for (int i = 0; i < 4; i++) {
        int idx = t + i*256;
        if (idx < 896) {                       // 56 rows x 16 quads
            int row = idx >> 4, q = idx & 15;
            CP_ASYNC16(bS + (uint32_t)(row*72 + q*4)*4,
                       &xb[(size_t)row*CCH + c0 + q*4]);
        }
    }
    CP_COMMIT();
}

__global__ void __launch_bounds__(256, 4) rfftWT_k(const float* __restrict__ x)
{
    extern __shared__ float sm[];
    uint32_t smem_base = smem_u32(sm);
    float* Cs = sm + RW_C;
    float* Ss = sm + RW_S;
    int bh = blockIdx.x;
    int t  = threadIdx.x;

    for (int i = t; i < 32*64; i += 256) {
        int r = i >> 6, c = i & 63;
        Cs[r*68+c] = g_Cwf[i]; Ss[r*68+c] = g_Swfn[i];
    }

    const float* xb = x + (size_t)bh*WW*CCH;
    int cbase = blockIdx.y * 4 * 64;

    rw_load(smem_base + (RW_X0 + 0*RW_BUF)*4, xb, cbase,      t);
    rw_load(smem_base + (RW_X0 + 1*RW_BUF)*4, xb, cbase + 64, t);

    int wid = t >> 5, lane = t & 31, g = lane >> 2, tig = lane & 3;
    int warpM = wid & 1, warpN = wid >> 1;   // 2 x 4 (N-tile 16)

    #pragma unroll 1
    for (int c = 0; c < 4; c++) {
        if (c == 3) { CP_WAIT(0); } else { CP_WAIT(1); }
        __syncthreads();
        const float* X = sm + RW_X0 + (c & 1)*RW_BUF;
        int c0 = cbase + c*64;

        float cr[2][4], ci[2][4];
        #pragma unroll
        for (int nt=0;nt<2;nt++)
            #pragma unroll
            for (int j=0;j<4;j++){ cr[nt][j]=0.f; ci[nt][j]=0.f; }

        #pragma unroll
        for (int ks = 0; ks < 7; ks++) {
            int row = warpM*16 + g, col = ks*8 + tig;
            uint32_t aC[4], aS[4];
            aC[0]=__float_as_uint(Cs[row*68+col]);     aC[1]=__float_as_uint(Cs[(row+8)*68+col]);
            aC[2]=__float_as_uint(Cs[row*68+col+4]);   aC[3]=__float_as_uint(Cs[(row+8)*68+col+4]);
            aS[0]=__float_as_uint(Ss[row*68+col]);     aS[1]=__float_as_uint(Ss[(row+8)*68+col]);
            aS[2]=__float_as_uint(Ss[row*68+col+4]);   aS[3]=__float_as_uint(Ss[(row+8)*68+col+4]);
            #pragma unroll
            for (int nt = 0; nt < 2; nt++) {
                int n = warpN*16 + nt*8 + g;
                uint32_t b0 = __float_as_uint(to_tf32(X[(ks*8+tig)*72 + n]));
                uint32_t b1 = __float_as_uint(to_tf32(X[(ks*8+tig+4)*72 + n]));
                mma1688(cr[nt], aC, b0, b1);
                mma1688(ci[nt], aS, b0, b1);
            }
        }

        size_t ob = (size_t)bh*WF*CCH + c0;
        #pragma unroll
        for (int nt = 0; nt < 2; nt++) {
            int n2 = warpN*16 + nt*8 + 2*tig;
            int k0r = warpM*16 + g, k1r = k0r + 8;
            float2 r0 = make_float2(to_tf32(cr[nt][0]), to_tf32(cr[nt][1]));
            float2 i0 = make_float2(to_tf32(ci[nt][0]), to_tf32(ci[nt][1]));
            *(float2*)&g_Ar[ob + (size_t)k0r*CCH + n2] = r0;
            *(float2*)&g_Ai[ob + (size_t)k0r*CCH + n2] = i0;
            if (k1r < WF) {
                float2 r1 = make_float2(to_tf32(cr[nt][2]), to_tf32(cr[nt][3]));
                float2 i1 = make_float2(to_tf32(ci[nt][2]), to_tf32(ci[nt][3]));
                *(float2*)&g_Ar[ob + (size_t)k1r*CCH + n2] = r1;
                *(float2*)&g_Ai[ob + (size_t)k1r*CCH + n2] = i1;
            }
        }

        if (c + 2 < 4) {
            __syncthreads();
            rw_load(smem_base + (RW_X0 + (c & 1)*RW_BUF)*4, xb, c0 + 128, t);
        }
    }
}

// ========== stage 2/5: FFT along H — reg-trig, 3 buffers, 1 barrier/chunk ====
// DIR=0: g_Ar/g_Ai -> fp16 g_hXr/g_hXi.  DIR=1: g_Br/g_Bi -> g_Ar/g_Ai (tf32).
#define FH_XI_OFF (56*72)           // 4032 within buffer
#define FH_BUF (2*56*72)            // 8064 floats
#define FH_TOT (3*FH_BUF*4)         // 96768 B -> 2 CTAs/SM
#define HROW (WF*CCH)   // 22272

__device__ __forceinline__ void fh_load(uint32_t bS,
                                        const float* __restrict__ inR,
                                        const float* __restrict__ inI,
                                        size_t gb, int t)
{
    #pragma unroll
    for (int i = 0; i < 7; i++) {          // 2 arrays x 56 rows x 16 quads = 1792 = 7*256
        int idx = t + i*256;
        int a = (idx >= 896) ? 1 : 0;
        int rem = idx - a*896;
        int row = rem >> 4, q = rem & 15;
        const float* src = a ? inI : inR;
        CP_ASYNC16(bS + (uint32_t)(a*FH_XI_OFF + row*72 + q*4)*4,
                   &src[gb + (size_t)row*HROW + q*4]);
    }
    CP_COMMIT();
}

template<int DIR>
__device__ __forceinline__ void fh_compute(const float* __restrict__ XR,
                                           const float* __restrict__ XI,
                                           const uint32_t aC[7][4], const uint32_t aS[7][4],
                                           size_t base, int warpM, int warpN, int g, int tig)
{
    float cr[4][4], ci[4][4];
    #pragma unroll
    for (int nt=0;nt<4;nt++)
        #pragma unroll
        for (int j=0;j<4;j++){ cr[nt][j]=0.f; ci[nt][j]=0.f; }

    #pragma unroll
    for (int ks = 0; ks < 7; ks++) {
        uint32_t aSn[4];
        #pragma unroll
        for (int j=0;j<4;j++) aSn[j] = aS[ks][j] ^ 0x80000000u;
        #pragma unroll
        for (int nt = 0; nt < 4; nt++) {
            int n = warpN*32 + nt*8 + g;
            uint32_t br0 = __float_as_uint(XR[(ks*8+tig)*72 + n]);
            uint32_t br1 = __float_as_uint(XR[(ks*8+tig+4)*72 + n]);
            uint32_t bi0 = __float_as_uint(XI[(ks*8+tig)*72 + n]);
            uint32_t bi1 = __float_as_uint(XI[(ks*8+tig+4)*72 + n]);
            mma1688(cr[nt], aC[ks],  br0, br1);
            mma1688(cr[nt], aS[ks],  bi0, bi1);
            mma1688(ci[nt], aC[ks],  bi0, bi1);
            mma1688(ci[nt], aSn,     br0, br1);
        }
    }

    int k0r = warpM*16 + g;
    #pragma unroll
    for (int nt = 0; nt < 4; nt++) {
        int n2 = warpN*32 + nt*8 + 2*tig;
        if (DIR == 0) {
            *(__half2*)&g_hXr[base + (size_t)k0r*HROW + n2] = __floats2half2_rn(cr[nt][0], cr[nt][1]);
            *(__half2*)&g_hXi[base + (size_t)k0r*HROW + n2] = __floats2half2_rn(ci[nt][0], ci[nt][1]);
            if (warpM < 3) {
                *(__half2*)&g_hXr[base + (size_t)(k0r+8)*HROW + n2] = __floats2half2_rn(cr[nt][2], cr[nt][3]);
                *(__half2*)&g_hXi[base + (size_t)(k0r+8)*HROW + n2] = __floats2half2_rn(ci[nt][2], ci[nt][3]);
            }
        } else {
            float2 r0 = make_float2(to_tf32(cr[nt][0]), to_tf32(cr[nt][1]));
            float2 i0 = make_float2(to_tf32(ci[nt][0]), to_tf32(ci[nt][1]));
            *(float2*)&g_Ar[base + (size_t)k0r*HROW + n2] = r0;
            *(float2*)&g_Ai[base + (size_t)k0r*HROW + n2] = i0;
            if (warpM < 3) {
                float2 r1 = make_float2(to_tf32(cr[nt][2]), to_tf32(cr[nt][3]));
                float2 i1 = make_float2(to_tf32(ci[nt][2]), to_tf32(ci[nt][3]));
                *(float2*)&g_Ar[base + (size_t)(k0r+8)*HROW + n2] = r1;
                *(float2*)&g_Ai[base + (size_t)(k0r+8)*HROW + n2] = i1;
            }
        }
    }
}

template<int DIR>
__global__ void __launch_bounds__(256, 2) fftHT_k()
{
    extern __shared__ float sm[];
    uint32_t smem_base = smem_u32(sm);
    int b  = blockIdx.x;
    int t  = threadIdx.x;

    const float* inR  = (DIR==0) ? g_Ar : g_Br;
    const float* inI  = (DIR==0) ? g_Ai : g_Bi;

    int wid = t >> 5, lane = t & 31, g = lane >> 2, tig = lane & 3;
    int warpM = wid & 3, warpN = wid >> 2;   // 4 x 2 (N-tile 32)

    uint32_t aC[7][4], aS[7][4];
    {
        int row = warpM*16 + g;
        #pragma unroll
        for (int ks = 0; ks < 7; ks++) {
            int col = ks*8 + tig;
            aC[ks][0]=__float_as_uint(g_Ch[row*64+col]);
            aC[ks][1]=__float_as_uint(g_Ch[(row+8)*64+col]);
            aC[ks][2]=__float_as_uint(g_Ch[row*64+col+4]);
            aC[ks][3]=__float_as_uint(g_Ch[(row+8)*64+col+4]);
            float s0=g_Sh[row*64+col],   s1=g_Sh[(row+8)*64+col];
            float s2=g_Sh[row*64+col+4], s3=g_Sh[(row+8)*64+col+4];
            if (DIR==1){ s0=-s0; s1=-s1; s2=-s2; s3=-s3; }
            aS[ks][0]=__float_as_uint(s0); aS[ks][1]=__float_as_uint(s1);
            aS[ks][2]=__float_as_uint(s2); aS[ks][3]=__float_as_uint(s3);
        }
    }

    size_t bbase = (size_t)b*HH*HROW;
    int jbase = blockIdx.y * 6 * 64;   // T=6

    fh_load(smem_base + (0*FH_BUF)*4, inR, inI, bbase + jbase,      t);
    fh_load(smem_base + (1*FH_BUF)*4, inR, inI, bbase + jbase + 64, t);

    #define FH_STEP(C, BUF, LOADBUF, DO_LOAD, LAST)                              \
        do {                                                                     \
            if (LAST) { CP_WAIT(0); } else { CP_WAIT(1); }                       \
            __syncthreads();                                                     \
            if (DO_LOAD)                                                         \
                fh_load(smem_base + (LOADBUF)*FH_BUF*4, inR, inI,                \
                        bbase + jbase + ((C)+2)*64, t);                          \
            fh_compute<DIR>(sm + (BUF)*FH_BUF, sm + (BUF)*FH_BUF + FH_XI_OFF,    \
                            aC, aS, bbase + jbase + (C)*64,                      \
                            warpM, warpN, g, tig);                               \
        } while (0)

    FH_STEP(0, 0, 2, true,  false);
    FH_STEP(1, 1, 0, true,  false);
    FH_STEP(2, 2, 1, true,  false);
    FH_STEP(3, 0, 2, true,  false);
    FH_STEP(4, 1, 0, false, false);
    FH_STEP(5, 2, 0, false, true);
    #undef FH_STEP
}

// ========== stage 6: inverse rfft along W — cp.async pipelined ===============
#define IW_C   0
#define IW_S   (64*36)
#define IW_B0  (2*64*36)           // 4608
#define IW_XI_OFF (32*72)          // 2304 within buffer
#define IW_BUF (2*32*72)           // 4608
#define IW_TOT ((2*64*36 + 2*2*32*72)*4)   // 55296 B -> 4 CTAs/SM

__device__ __forceinline__ void iw_load(uint32_t bS, size_t gb, int t)
{
    #pragma unroll
    for (int i = 0; i < 4; i++) {          // 2 arrays x 29 rows x 16 quads = 928
        int idx = t + i*256;
        if (idx < 928) {
            int a = (idx >= 464) ? 1 : 0;
            int rem = idx - a*464;
            int row = rem >> 4, q = rem & 15;
            const float* src = a ? g_Ai : g_Ar;
            CP_ASYNC16(bS + (uint32_t)(a*IW_XI_OFF + row*72 + q*4)*4,
                       &src[gb + (size_t)row*CCH + q*4]);
        }
    }
    CP_COMMIT();
}

__global__ void __launch_bounds__(256, 4) irfftWT_k(float* __restrict__ out)
{
    extern __shared__ float sm[];
    uint32_t smem_base = smem_u32(sm);
    float* Cs = sm + IW_C;
    float* Ss = sm + IW_S;
    int bh = blockIdx.x;
    int t  = threadIdx.x;

    for (int i = t; i < 64*32; i += 256) {
        int r = i >> 5, c = i & 31;
        Cs[r*36+c] = g_Cw2[i]; Ss[r*36+c] = g_Sw2n[i];
    }
    for (int i = t; i < 2*2*3*72; i += 256) {
        int bu = i / (2*3*72);
        int rem = i % (2*3*72);
        int a  = rem / (3*72);
        int rr = rem % (3*72);
        sm[IW_B0 + bu*IW_BUF + a*IW_XI_OFF + (29 + rr/72)*72 + (rr%72)] = 0.f;
    }
    __syncthreads();

    size_t ibase = (size_t)bh*WF*CCH;
    int cbase = blockIdx.y * 4 * 64;

    iw_load(smem_base + (IW_B0 + 0*IW_BUF)*4, ibase + cbase,      t);
    iw_load(smem_base + (IW_B0 + 1*IW_BUF)*4, ibase + cbase + 64, t);

    int wid = t >> 5, lane = t & 31, g = lane >> 2, tig = lane & 3;
    int warpM = wid & 3, warpN = wid >> 2;   // 4 x 2 (N-tile 32)

    #pragma unroll 1
    for (int c = 0; c < 4; c++) {
        if (c == 3) { CP_WAIT(0); } else { CP_WAIT(1); }
        __syncthreads();
        const float* XR = sm + IW_B0 + (c & 1)*IW_BUF;
        const float* XI = XR + IW_XI_OFF;
        int c0 = cbase + c*64;

        float co[4][4];
        #pragma unroll
        for (int nt=0;nt<4;nt++)
            #pragma unroll
            for (int j=0;j<4;j++) co[nt][j]=0.f;

        #pragma unroll
        for (int ks = 0; ks < 4; ks++) {
            int row = warpM*16 + g, col = ks*8 + tig;
            uint32_t aC[4], aS[4];
            aC[0]=__float_as_uint(Cs[row*36+col]);     aC[1]=__float_as_uint(Cs[(row+8)*36+col]);
            aC[2]=__float_as_uint(Cs[row*36+col+4]);   aC[3]=__float_as_uint(Cs[(row+8)*36+col+4]);
            aS[0]=__float_as_uint(Ss[row*36+col]);     aS[1]=__float_as_uint(Ss[(row+8)*36+col]);
            aS[2]=__float_as_uint(Ss[row*36+col+4]);   aS[3]=__float_as_uint(Ss[(row+8)*36+col+4]);
            #pragma unroll
            for (int nt = 0; nt < 4; nt++) {
                int n = warpN*32 + nt*8 + g;
                uint32_t br0 = __float_as_uint(XR[(ks*8+tig)*72 + n]);
                uint32_t br1 = __float_as_uint(XR[(ks*8+tig+4)*72 + n]);
                uint32_t bi0 = __float_as_uint(XI[(ks*8+tig)*72 + n]);
                uint32_t bi1 = __float_as_uint(XI[(ks*8+tig+4)*72 + n]);
                mma1688(co[nt], aC, br0, br1);
                mma1688(co[nt], aS, bi0, bi1);
            }
        }

        int w0 = warpM*16 + g;
        size_t ob = (size_t)bh*WW*CCH + c0;
        #pragma unroll
        for (int nt = 0; nt < 4; nt++) {
            int n2 = warpN*32 + nt*8 + 2*tig;
            *(float2*)&out[ob + (size_t)w0*CCH + n2] = make_float2(co[nt][0], co[nt][1]);
            if (warpM < 3)
                *(float2*)&out[ob + (size_t)(w0+8)*CCH + n2] = make_float2(co[nt][2], co[nt][3]);
        }

        if (c + 2 < 4) {
            __syncthreads();
            iw_load(smem_base + (IW_B0 + (c & 1)*IW_BUF)*4, ibase + c0 + 128, t);
        }
    }
}

// ========== MLP GEMM: fp16 m16n8k16, 128x128, K-chunk 64, 3-stage ===========
#define HSTG 18432                    // halfs per stage (A 9216 + B 9216), stride 72
#define HBIAS_B 110592                // byte offset of fp32 bias (3 stages * 36864 B)
#define GEMM_SMEM (110592 + 512)      // 111104 B (2 CTAs/SM)

template<int LAYER>
__device__ __forceinline__ void gload(int blk, int p0, int n0, int kc,
                                      uint32_t aS, uint32_t bS, int t)
{
    const __half* inR = (LAYER==1) ? g_hXr : g_hHr;
    const __half* inI = (LAYER==1) ? g_hXi : g_hHi;
    const __half* Wt  = ((LAYER==1) ? g_hW1 : g_hW2) + (size_t)blk*384*384;
    const __half* src = (kc < 3) ? inR : inI;
    int koff = blk*192 + ((kc < 3) ? kc*64 : (kc-3)*64);
    #pragma unroll
    for (int i = 0; i < 4; i++) {      // A: 128 rows x 8 quads (128 B/row)
        int idx = t + i*256;
        int r = idx >> 3, q = idx & 7;
        CP_ASYNC16(aS + (uint32_t)(r*144 + q*16),
                   &src[(size_t)(p0+r)*CCH + koff + q*8]);
    }
    int kb = kc*64;
    #pragma unroll
    for (int i = 0; i < 4; i++) {      // B: 128 rows x 8 quads
        int idx = t + i*256;
        int r = idx >> 3, q = idx & 7;
        CP_ASYNC16(bS + (uint32_t)(r*144 + q*16),
                   &Wt[(size_t)(n0+r)*384 + kb + q*8]);
    }
}

__device__ __forceinline__ void gcompute(const __half* __restrict__ As,
                                         const __half* __restrict__ Bs,
                                         float c[4][4][4],
                                         int warpM, int warpN, int g, int tig)
{
    #pragma unroll
    for (int ks = 0; ks < 4; ks++) {   // 64 halfs per chunk = 4 k16 steps
        int col = ks*16 + 2*tig;
        uint32_t a[4][4];
        #pragma unroll
        for (int mt = 0; mt < 4; mt++) {
            int r = warpM*64 + mt*16 + g;
            a[mt][0] = *(const uint32_t*)&As[r*72 + col];
            a[mt][1] = *(const uint32_t*)&As[(r+8)*72 + col];
            a[mt][2] = *(const uint32_t*)&As[r*72 + col + 8];
            a[mt][3] = *(const uint32_t*)&As[(r+8)*72 + col + 8];
        }
        #pragma unroll
        for (int nt = 0; nt < 4; nt++) {
            int n = warpN*32 + nt*8 + g;
            uint32_t b0 = *(const uint32_t*)&Bs[n*72 + col];
            uint32_t b1 = *(const uint32_t*)&Bs[n*72 + col + 8];
            #pragma unroll
            for (int mt = 0; mt < 4; mt++)
                mma16816(c[mt][nt], a[mt], b0, b1);
        }
    }
}

template<int LAYER>
__global__ void __launch_bounds__(256, 2) gemmM_k()
{
    extern __shared__ char smc[];
    __half* smh = (__half*)smc;
    float* sbias = (float*)(smc + HBIAS_B);
    uint32_t smem_base = smem_u32(smc);
    int t = threadIdx.x;
    int wid = t >> 5, lane = t & 31;
    int g = lane >> 2, tig = lane & 3;
    int warpM = wid & 1, warpN = wid >> 1;   // 2 x 4, 64x32 per warp
    int n0  = blockIdx.x * 128;
    int p0  = blockIdx.y * 128;
    int blk = blockIdx.z;

    const float* bias = ((LAYER==1) ? g_b1 : g_b2) + blk*384;
    if (t < 128) sbias[t] = bias[n0 + t];

    float c[4][4][4];
    #pragma unroll
    for (int mt=0;mt<4;mt++)
        #pragma unroll
        for (int nt=0;nt<4;nt++)
            #pragma unroll
            for (int j=0;j<4;j++) c[mt][nt][j] = 0.f;

    gload<LAYER>(blk, p0, n0, 0, smem_base + (0*HSTG)*2, smem_base + (0*HSTG + 9216)*2, t);
    CP_COMMIT();
    gload<LAYER>(blk, p0, n0, 1, smem_base + (1*HSTG)*2, smem_base + (1*HSTG + 9216)*2, t);
    CP_COMMIT();

    // chunk kc uses buffer kc%3; load kc+2 into (kc+2)%3 after barrier.
    #define GEMM_STEP(KC, BUF, LBUF, DO_LOAD, WAITN)                            \
        do {                                                                    \
            CP_WAIT(WAITN);                                                     \
            __syncthreads();                                                    \
            if (DO_LOAD) {                                                      \
                gload<LAYER>(blk, p0, n0, (KC)+2,                               \
                             smem_base + ((LBUF)*HSTG)*2,                       \
                             smem_base + ((LBUF)*HSTG + 9216)*2, t);            \
                CP_COMMIT();                                                    \
            }                                                                   \
            gcompute(smh + (BUF)*HSTG, smh + (BUF)*HSTG + 9216,                 \
                     c, warpM, warpN, g, tig);                                  \
        } while (0)

    GEMM_STEP(0, 0, 2, true,  1);
    GEMM_STEP(1, 1, 0, true,  1);
    GEMM_STEP(2, 2, 1, true,  1);
    GEMM_STEP(3, 0, 2, true,  1);
    GEMM_STEP(4, 1, 0, false, 1);
    GEMM_STEP(5, 2, 0, false, 0);
    #undef GEMM_STEP

    #pragma unroll
    for (int mt = 0; mt < 4; mt++) {
        #pragma unroll
        for (int rr = 0; rr < 2; rr++) {
            int r = p0 + warpM*64 + mt*16 + rr*8 + g;
            size_t rowoff = (size_t)r*CCH + blk*192;
            #pragma unroll
            for (int nt = 0; nt < 4; nt++) {
                int kl = warpN*32 + nt*8 + 2*tig;
                int ko = n0 + kl;
                float v0 = c[mt][nt][rr*2+0] + sbias[kl];
                float v1 = c[mt][nt][rr*2+1] + sbias[kl + 1];
                int kr = (ko < 192) ? ko : ko - 192;
                if (LAYER == 1) {
                    v0 = fmaxf(v0, 0.f);
                    v1 = fmaxf(v1, 0.f);
                    __half* dst = (ko < 192) ? g_hHr : g_hHi;
                    *(__half2*)&dst[rowoff + kr] = __floats2half2_rn(v0, v1);
                } else {
                    v0 = to_tf32((v0 >  SSHRINK) ? v0-SSHRINK : ((v0 < -SSHRINK) ? v0+SSHRINK : 0.f));
                    v1 = to_tf32((v1 >  SSHRINK) ? v1-SSHRINK : ((v1 < -SSHRINK) ? v1+SSHRINK : 0.f));
                    float* dst = (ko < 192) ? g_Br : g_Bi;
                    *(float2*)&dst[rowoff + kr] = make_float2(v0, v1);
                }
            }
        }
    }
}

// ---------------- launch ------------------------------------------------------
extern "C" void kernel_launch(void* const* d_in, const int* in_sizes, int n_in,
                              void* d_out, int out_size)
{
    const float* x  = (const float*)d_in[0];
    const float* w1 = (const float*)d_in[1];
    const float* b1 = (const float*)d_in[2];
    const float* w2 = (const float*)d_in[3];
    const float* b2 = (const float*)d_in[4];
    float* out = (float*)d_out;

    cudaFuncSetAttribute((const void*)rfftWT_k,   cudaFuncAttributeMaxDynamicSharedMemorySize, RW_TOT);
    cudaFuncSetAttribute((const void*)fftHT_k<0>, cudaFuncAttributeMaxDynamicSharedMemorySize, FH_TOT);
    cudaFuncSetAttribute((const void*)fftHT_k<1>, cudaFuncAttributeMaxDynamicSharedMemorySize, FH_TOT);
    cudaFuncSetAttribute((const void*)irfftWT_k,  cudaFuncAttributeMaxDynamicSharedMemorySize, IW_TOT);
    cudaFuncSetAttribute((const void*)gemmM_k<1>, cudaFuncAttributeMaxDynamicSharedMemorySize, GEMM_SMEM);
    cudaFuncSetAttribute((const void*)gemmM_k<2>, cudaFuncAttributeMaxDynamicSharedMemorySize, GEMM_SMEM);

    init_k<<<512, 256>>>(w1, b1, w2, b2);
    rfftWT_k<<<dim3(BB*HH, 3), 256, RW_TOT>>>(x);
    fftHT_k<0><<<dim3(BB, 58), 256, FH_TOT>>>();
    gemmM_k<1><<<dim3(3, 406, NBLK), 256, GEMM_SMEM>>>();
    gemmM_k<2><<<dim3(3, 406, NBLK), 256, GEMM_SMEM>>>();
    fftHT_k<1><<<dim3(BB, 58), 256, FH_TOT>>>();
    irfftWT_k<<<dim3(BB*HH, 3), 256, IW_TOT>>>(out);
}